// round 1
// baseline (speedup 1.0000x reference)
#include <cuda_runtime.h>

#define Bb 8
#define Nn 1024
#define Ff 256
#define Hh 4
#define Uu 256

#define BM 128
#define BN 128
#define BK 16
#define ASMP 20   // padded A-tile stride (float4-aligned)

// Scratch (static device globals — no allocation)
__device__ float g_h[(size_t)Bb * Hh * Nn * Uu];   // 32 MB: per-head projections
__device__ float g_src[Bb * Hh * Nn];
__device__ float g_dst[Bb * Hh * Nn];

// ---------------------------------------------------------------------------
// Kernel 1: h[b,h,n,u] = sum_f x[b,n,f] * W[h,f,u]
// Classic smem-tiled fp32 GEMM, 128x128 block tile, 8x8 microtile, 256 threads.
// ---------------------------------------------------------------------------
__global__ __launch_bounds__(256) void proj_kernel(const float* __restrict__ x,
                                                   const float* __restrict__ W) {
    int bh = blockIdx.z;
    int b = bh >> 2, h = bh & 3;
    const float* A = x + (size_t)b * Nn * Ff;        // [N,F] row-major
    const float* Bm = W + (size_t)h * Ff * Uu;       // [F,U] row-major
    float* C = g_h + (size_t)bh * Nn * Uu;

    int i0 = blockIdx.x * BM;
    int j0 = blockIdx.y * BN;

    __shared__ float As[BM][ASMP];
    __shared__ float Bs[BK][BN];

    float acc[8][8];
#pragma unroll
    for (int r = 0; r < 8; r++)
#pragma unroll
        for (int c = 0; c < 8; c++) acc[r][c] = 0.f;

    int tid = threadIdx.x;
    int ty = tid >> 4, tx = tid & 15;

    for (int k0 = 0; k0 < Ff; k0 += BK) {
        // A tile: 128 rows x 16 cols, float4 loads
#pragma unroll
        for (int t = 0; t < 2; t++) {
            int idx4 = t * 256 + tid;
            int row = idx4 >> 2, c4 = (idx4 & 3) << 2;
            float4 v = *(const float4*)&A[(size_t)(i0 + row) * Ff + k0 + c4];
            *(float4*)&As[row][c4] = v;
        }
        // B tile: 16 rows x 128 cols, float4 loads (coalesced)
#pragma unroll
        for (int t = 0; t < 2; t++) {
            int idx4 = t * 256 + tid;
            int row = idx4 >> 5, c4 = (idx4 & 31) << 2;
            float4 v = *(const float4*)&Bm[(size_t)(k0 + row) * Uu + j0 + c4];
            *(float4*)&Bs[row][c4] = v;
        }
        __syncthreads();

#pragma unroll
        for (int kk = 0; kk < BK; kk++) {
            float a[8];
#pragma unroll
            for (int r = 0; r < 8; r++) a[r] = As[ty * 8 + r][kk];
            float4 b0 = *(const float4*)&Bs[kk][tx * 8];
            float4 b1 = *(const float4*)&Bs[kk][tx * 8 + 4];
            float bb[8] = {b0.x, b0.y, b0.z, b0.w, b1.x, b1.y, b1.z, b1.w};
#pragma unroll
            for (int r = 0; r < 8; r++)
#pragma unroll
                for (int c = 0; c < 8; c++)
                    acc[r][c] = fmaf(a[r], bb[c], acc[r][c]);
        }
        __syncthreads();
    }

#pragma unroll
    for (int r = 0; r < 8; r++) {
        int i = i0 + ty * 8 + r;
        float4 o0 = make_float4(acc[r][0], acc[r][1], acc[r][2], acc[r][3]);
        float4 o1 = make_float4(acc[r][4], acc[r][5], acc[r][6], acc[r][7]);
        *(float4*)&C[(size_t)i * Uu + j0 + tx * 8] = o0;
        *(float4*)&C[(size_t)i * Uu + j0 + tx * 8 + 4] = o1;
    }
}

// ---------------------------------------------------------------------------
// Kernel 2: src[row] = h_row . a_src[h],  dst[row] = h_row . a_dst[h]
// One warp per row (row = bh*N + n).
// ---------------------------------------------------------------------------
__global__ __launch_bounds__(128) void srcdst_kernel(const float* __restrict__ a_src,
                                                     const float* __restrict__ a_dst) {
    int warp = threadIdx.x >> 5, lane = threadIdx.x & 31;
    int row = blockIdx.x * 4 + warp;                 // [0, B*H*N)
    int h = (row / Nn) & 3;
    const float* hp = g_h + (size_t)row * Uu;
    const float* as = a_src + h * Uu;
    const float* ad = a_dst + h * Uu;

    float s1 = 0.f, s2 = 0.f;
#pragma unroll
    for (int u = lane * 4; u < Uu; u += 128) {
        float4 v = *(const float4*)&hp[u];
        float4 p = *(const float4*)&as[u];
        float4 q = *(const float4*)&ad[u];
        s1 += v.x * p.x + v.y * p.y + v.z * p.z + v.w * p.w;
        s2 += v.x * q.x + v.y * q.y + v.z * q.z + v.w * q.w;
    }
#pragma unroll
    for (int o = 16; o > 0; o >>= 1) {
        s1 += __shfl_down_sync(0xffffffffu, s1, o);
        s2 += __shfl_down_sync(0xffffffffu, s2, o);
    }
    if (lane == 0) { g_src[row] = s1; g_dst[row] = s2; }
}

// ---------------------------------------------------------------------------
// Kernel 3: fused attention.
// scores s_ij = lrelu(src_i + dst_j). lrelu is monotone, so the exact softmax
// row-max is m_i = lrelu(src_i + max_j dst_j) — single pass, no rescaling.
// Block computes C[128 i, 128 u] = sum_j exp(s_ij - m_i) * h[j,u], then
// divides by the exact rowsum and writes the transposed output.
// ---------------------------------------------------------------------------
__global__ __launch_bounds__(256) void attn_kernel(float* __restrict__ out) {
    int bh = blockIdx.z;
    int b = bh >> 2, h = bh & 3;
    int i0 = blockIdx.x * BM;
    int j0 = blockIdx.y * BN;                        // u offset
    const float* V = g_h + (size_t)bh * Nn * Uu;
    const float* src = g_src + bh * Nn;
    const float* dst = g_dst + bh * Nn;

    __shared__ float Ws[BK][BM];    // k-major attn-weight tile (bank = i%32)
    __shared__ float Vs[BK][BN];
    __shared__ float red[256];
    __shared__ float s_m[BM];       // m_i, later reused as 1/rowsum_i
    __shared__ float s_src[BM];
    __shared__ float s_rs[256];

    int tid = threadIdx.x;

    // dmax = max_j dst_j  (per b,h; redundantly per block, trivially cheap)
    float lm = -3.4e38f;
#pragma unroll
    for (int t = 0; t < 4; t++) lm = fmaxf(lm, dst[tid + t * 256]);
    red[tid] = lm;
    __syncthreads();
    for (int s = 128; s > 0; s >>= 1) {
        if (tid < s) red[tid] = fmaxf(red[tid], red[tid + s]);
        __syncthreads();
    }
    float dmax = red[0];
    if (tid < BM) {
        float sv = src[i0 + tid];
        s_src[tid] = sv;
        float t = sv + dmax;
        s_m[tid] = fmaxf(t, 0.2f * t);               // exact row max of lrelu scores
    }
    __syncthreads();

    float acc[8][8];
#pragma unroll
    for (int r = 0; r < 8; r++)
#pragma unroll
        for (int c = 0; c < 8; c++) acc[r][c] = 0.f;

    float prs = 0.f;                 // partial rowsum for this thread's fixed i
    int ty = tid >> 4, tx = tid & 15;
    int wi = tid & 127;              // fixed i for weight generation
    int wk0 = (tid >> 7) * 8;        // k base (0 or 8) within the 16-wide tile
    float my_src = s_src[wi];
    float my_m = s_m[wi];

    for (int k0 = 0; k0 < Nn; k0 += BK) {
        // Generate attention-weight tile on the fly (k-major store: conflict-free)
#pragma unroll
        for (int t = 0; t < 8; t++) {
            int k = wk0 + t;
            float s = my_src + dst[k0 + k];
            s = fmaxf(s, 0.2f * s);                  // leaky_relu(0.2)
            float w = __expf(s - my_m);              // <= 1 always
            Ws[k][wi] = w;
            prs += w;
        }
        // Load V tile (rows j = k0..k0+15, 128 contiguous u cols)
#pragma unroll
        for (int t = 0; t < 2; t++) {
            int idx4 = t * 256 + tid;
            int row = idx4 >> 5, c4 = (idx4 & 31) << 2;
            float4 v = *(const float4*)&V[(size_t)(k0 + row) * Uu + j0 + c4];
            *(float4*)&Vs[row][c4] = v;
        }
        __syncthreads();

#pragma unroll
        for (int kk = 0; kk < BK; kk++) {
            float a[8];
#pragma unroll
            for (int r = 0; r < 8; r++) a[r] = Ws[kk][ty * 8 + r];
            float4 b0 = *(const float4*)&Vs[kk][tx * 8];
            float4 b1 = *(const float4*)&Vs[kk][tx * 8 + 4];
            float bb[8] = {b0.x, b0.y, b0.z, b0.w, b1.x, b1.y, b1.z, b1.w};
#pragma unroll
            for (int r = 0; r < 8; r++)
#pragma unroll
                for (int c = 0; c < 8; c++)
                    acc[r][c] = fmaf(a[r], bb[c], acc[r][c]);
        }
        __syncthreads();
    }

    // Exact rowsum: thread tid and tid+128 share the same i
    s_rs[tid] = prs;
    __syncthreads();
    if (tid < 128) s_m[tid] = 1.0f / (s_rs[tid] + s_rs[tid + 128]);
    __syncthreads();

    // Normalized epilogue, written directly into [B, N, H*U]
#pragma unroll
    for (int r = 0; r < 8; r++) {
        int i = ty * 8 + r;
        float inv = s_m[i];
        int ig = i0 + i;
        size_t off = ((size_t)(b * Nn + ig)) * (Hh * Uu) + h * Uu + j0 + tx * 8;
        float4 o0 = make_float4(acc[r][0] * inv, acc[r][1] * inv,
                                acc[r][2] * inv, acc[r][3] * inv);
        float4 o1 = make_float4(acc[r][4] * inv, acc[r][5] * inv,
                                acc[r][6] * inv, acc[r][7] * inv);
        *(float4*)&out[off] = o0;
        *(float4*)&out[off + 4] = o1;
    }
}

// ---------------------------------------------------------------------------
extern "C" void kernel_launch(void* const* d_in, const int* in_sizes, int n_in,
                              void* d_out, int out_size) {
    (void)in_sizes; (void)n_in; (void)out_size;
    const float* x     = (const float*)d_in[0];
    const float* W     = (const float*)d_in[1];
    const float* a_src = (const float*)d_in[2];
    const float* a_dst = (const float*)d_in[3];
    float* out = (float*)d_out;

    dim3 gproj(Nn / BM, Uu / BN, Bb * Hh);   // (8, 2, 32)
    proj_kernel<<<gproj, 256>>>(x, W);
    srcdst_kernel<<<(Bb * Hh * Nn) / 4, 128>>>(a_src, a_dst);
    dim3 gattn(Nn / BM, Uu / BN, Bb * Hh);   // (8, 2, 32)
    attn_kernel<<<gattn, 256>>>(out);
}

// round 5
// speedup vs baseline: 1.7757x; 1.7757x over previous
#include <cuda_runtime.h>
#include <cuda_bf16.h>
#include <cstdint>

#define Bb 8
#define Nn 1024
#define Ff 256
#define Hh 4
#define Uu 256
#define BHt (Bb * Hh)

// ---------------- device scratch (static, no allocation) ----------------
__device__ float g_h[(size_t)BHt * Nn * Uu];               // fp32 projections [bh][n][u]
__device__ float g_src[BHt * Nn];
__device__ float g_dst[BHt * Nn];
__device__ __nv_bfloat16 g_vt_hi[(size_t)BHt * Uu * Nn];   // h^T split [bh][u][n]
__device__ __nv_bfloat16 g_vt_lo[(size_t)BHt * Uu * Nn];
__device__ __nv_bfloat16 g_wt_hi[Hh * Uu * Ff];            // W^T split [h][u][f]
__device__ __nv_bfloat16 g_wt_lo[Hh * Uu * Ff];
__device__ float g_Q[BHt * Nn];                            // exp(dst - dmax)
__device__ float g_S[BHt * Nn];                            // exp(0.2(dst - dmax))
__device__ float g_P[BHt * Nn];                            // exp(T - m), T=src+dmax
__device__ float g_Rr[BHt * Nn];                           // exp(0.2T - m)
__device__ float g_thr[BHt * Nn];                          // -src
__device__ float g_inv[BHt * Nn];                          // 1/rowsum

// ---------------- helpers ----------------
__device__ __forceinline__ void split_pack(float w0, float w1, uint32_t& hi, uint32_t& lo) {
    __nv_bfloat16 h0 = __float2bfloat16(w0), h1 = __float2bfloat16(w1);
    float l0 = w0 - __bfloat162float(h0);
    float l1 = w1 - __bfloat162float(h1);
    __nv_bfloat162 hp = __halves2bfloat162(h0, h1);
    __nv_bfloat162 lp = __halves2bfloat162(__float2bfloat16(l0), __float2bfloat16(l1));
    hi = *reinterpret_cast<uint32_t*>(&hp);
    lo = *reinterpret_cast<uint32_t*>(&lp);
}
__device__ __forceinline__ void mma16816(float* c, const uint32_t* a, uint32_t b0, uint32_t b1) {
    asm volatile(
        "mma.sync.aligned.m16n8k16.row.col.f32.bf16.bf16.f32 "
        "{%0,%1,%2,%3}, {%4,%5,%6,%7}, {%8,%9}, {%0,%1,%2,%3};"
        : "+f"(c[0]), "+f"(c[1]), "+f"(c[2]), "+f"(c[3])
        : "r"(a[0]), "r"(a[1]), "r"(a[2]), "r"(a[3]), "r"(b0), "r"(b1));
}

// ================== prep: W^T split bf16 [h][u][f] ==================
__global__ __launch_bounds__(256) void prep_wt_kernel(const float* __restrict__ W) {
    int idx = blockIdx.x * 256 + threadIdx.x;        // [0, H*U*F)
    int f = idx & 255, u = (idx >> 8) & 255, h = idx >> 16;
    float w = W[((size_t)(h * 256 + f)) * 256 + u];
    __nv_bfloat16 hi = __float2bfloat16(w);
    __nv_bfloat16 lo = __float2bfloat16(w - __bfloat162float(hi));
    size_t o = ((size_t)(h * 256 + u)) * 256 + f;
    g_wt_hi[o] = hi;
    g_wt_lo[o] = lo;
}

// ================== proj: h = x @ W via mma.sync (split bf16) ==================
// grid (8 i-tiles, 2 u-tiles, 32 bh), 256 threads (8 warps: 4 m x 2 n)
__global__ __launch_bounds__(256) void proj_mma_kernel(const float* __restrict__ x) {
    __shared__ float xs[32][132];                      // [k][i], conflict-free frag reads
    __shared__ __nv_bfloat16 WTh[128][36];             // [u][k] stage
    __shared__ __nv_bfloat16 WTl[128][36];

    int tid = threadIdx.x;
    int warp = tid >> 5, lane = tid & 31;
    int warp_m = warp & 3, warp_n = warp >> 2;
    int bh = blockIdx.z, b = bh >> 2, h = bh & 3;
    int i0 = blockIdx.x * 128, u0 = blockIdx.y * 128;

    float acc[2][8][4];
#pragma unroll
    for (int mt = 0; mt < 2; mt++)
#pragma unroll
        for (int nt = 0; nt < 8; nt++)
#pragma unroll
            for (int q = 0; q < 4; q++) acc[mt][nt][q] = 0.f;

    for (int st = 0; st < 8; st++) {                   // k stages of 32 (F=256)
        int f0 = st * 32;
        __syncthreads();
        // stage x tile [128 i][32 k] -> xs[k][i]
#pragma unroll
        for (int it = 0; it < 4; it++) {
            int task = tid + it * 256;                 // 1024 tasks
            int i = task >> 3, c4 = (task & 7) << 2;
            float4 v = *(const float4*)&x[((size_t)(b * Nn + i0 + i)) * Ff + f0 + c4];
            xs[c4 + 0][i] = v.x;
            xs[c4 + 1][i] = v.y;
            xs[c4 + 2][i] = v.z;
            xs[c4 + 3][i] = v.w;
        }
        // stage W^T slice [128 u][32 k] hi/lo
        {
            int row = tid >> 1, half = tid & 1;
            size_t gb = ((size_t)(h * 256 + u0 + row)) * 256 + f0 + half * 16;
            float4 vh0 = *(const float4*)(g_wt_hi + gb);
            float4 vh1 = *(const float4*)(g_wt_hi + gb + 8);
            float4 vl0 = *(const float4*)(g_wt_lo + gb);
            float4 vl1 = *(const float4*)(g_wt_lo + gb + 8);
            float2* dh = (float2*)&WTh[row][half * 16];
            float2* dl = (float2*)&WTl[row][half * 16];
            dh[0] = make_float2(vh0.x, vh0.y); dh[1] = make_float2(vh0.z, vh0.w);
            dh[2] = make_float2(vh1.x, vh1.y); dh[3] = make_float2(vh1.z, vh1.w);
            dl[0] = make_float2(vl0.x, vl0.y); dl[1] = make_float2(vl0.z, vl0.w);
            dl[2] = make_float2(vl1.x, vl1.y); dl[3] = make_float2(vl1.z, vl1.w);
        }
        __syncthreads();

#pragma unroll
        for (int kk = 0; kk < 2; kk++) {               // two k16 steps per stage
            int c = kk * 16 + (lane & 3) * 2;          // stage-local k
            uint32_t aH[2][4], aL[2][4];
#pragma unroll
            for (int mt = 0; mt < 2; mt++) {
                int r0 = warp_m * 32 + mt * 16 + (lane >> 2);
                int r1 = r0 + 8;
                split_pack(xs[c][r0],     xs[c + 1][r0], aH[mt][0], aL[mt][0]);
                split_pack(xs[c][r1],     xs[c + 1][r1], aH[mt][1], aL[mt][1]);
                split_pack(xs[c + 8][r0], xs[c + 9][r0], aH[mt][2], aL[mt][2]);
                split_pack(xs[c + 8][r1], xs[c + 9][r1], aH[mt][3], aL[mt][3]);
            }
#pragma unroll
            for (int nt = 0; nt < 8; nt++) {
                int un = warp_n * 64 + nt * 8 + (lane >> 2);
                int kc = kk * 16 + (lane & 3) * 2;
                uint32_t bh0 = *(uint32_t*)&WTh[un][kc];
                uint32_t bh1 = *(uint32_t*)&WTh[un][kc + 8];
                uint32_t bl0 = *(uint32_t*)&WTl[un][kc];
                uint32_t bl1 = *(uint32_t*)&WTl[un][kc + 8];
#pragma unroll
                for (int mt = 0; mt < 2; mt++) {
                    mma16816(acc[mt][nt], aH[mt], bh0, bh1);
                    mma16816(acc[mt][nt], aL[mt], bh0, bh1);
                    mma16816(acc[mt][nt], aH[mt], bl0, bl1);
                }
            }
        }
    }

    // epilogue -> g_h
#pragma unroll
    for (int mt = 0; mt < 2; mt++) {
        int i_lo = i0 + warp_m * 32 + mt * 16 + (lane >> 2);
#pragma unroll
        for (int nt = 0; nt < 8; nt++) {
            int u = u0 + warp_n * 64 + nt * 8 + (lane & 3) * 2;
            *(float2*)&g_h[((size_t)bh * Nn + i_lo) * Uu + u] =
                make_float2(acc[mt][nt][0], acc[mt][nt][1]);
            *(float2*)&g_h[((size_t)bh * Nn + i_lo + 8) * Uu + u] =
                make_float2(acc[mt][nt][2], acc[mt][nt][3]);
        }
    }
}

// ================== srcdst GEMV (validated in R1) ==================
__global__ __launch_bounds__(128) void srcdst_kernel(const float* __restrict__ a_src,
                                                     const float* __restrict__ a_dst) {
    int warp = threadIdx.x >> 5, lane = threadIdx.x & 31;
    int row = blockIdx.x * 4 + warp;
    int h = (row / Nn) & 3;
    const float* hp = g_h + (size_t)row * Uu;
    const float* as = a_src + h * Uu;
    const float* ad = a_dst + h * Uu;
    float s1 = 0.f, s2 = 0.f;
#pragma unroll
    for (int u = lane * 4; u < Uu; u += 128) {
        float4 v = *(const float4*)&hp[u];
        float4 p = *(const float4*)&as[u];
        float4 q = *(const float4*)&ad[u];
        s1 += v.x * p.x + v.y * p.y + v.z * p.z + v.w * p.w;
        s2 += v.x * q.x + v.y * q.y + v.z * q.z + v.w * q.w;
    }
#pragma unroll
    for (int o = 16; o > 0; o >>= 1) {
        s1 += __shfl_down_sync(0xffffffffu, s1, o);
        s2 += __shfl_down_sync(0xffffffffu, s2, o);
    }
    if (lane == 0) { g_src[row] = s1; g_dst[row] = s2; }
}

// ================== transpose + split: g_vt = split(h^T) ==================
__global__ __launch_bounds__(256) void transpose_split_kernel() {
    __shared__ float t[32][33];
    int bh = blockIdx.z;
    int n0 = blockIdx.x * 32, u0 = blockIdx.y * 32;
    int tx = threadIdx.x, ty = threadIdx.y;            // 32 x 8
#pragma unroll
    for (int r = 0; r < 32; r += 8)
        t[ty + r][tx] = g_h[((size_t)bh * Nn + n0 + ty + r) * Uu + u0 + tx];
    __syncthreads();
#pragma unroll
    for (int r = 0; r < 32; r += 8) {
        float v = t[tx][ty + r];
        __nv_bfloat16 hi = __float2bfloat16(v);
        __nv_bfloat16 lo = __float2bfloat16(v - __bfloat162float(hi));
        size_t o = ((size_t)bh * Uu + u0 + ty + r) * Nn + n0 + tx;
        g_vt_hi[o] = hi;
        g_vt_lo[o] = lo;
    }
}

// ================== prep P/Q/R/S/thr per (b,h) ==================
__global__ __launch_bounds__(1024) void prep_pqrs_kernel() {
    __shared__ float red[1024];
    int bh = blockIdx.x, tid = threadIdx.x;
    float d = g_dst[bh * Nn + tid];
    red[tid] = d;
    __syncthreads();
    for (int s = 512; s > 0; s >>= 1) {
        if (tid < s) red[tid] = fmaxf(red[tid], red[tid + s]);
        __syncthreads();
    }
    float dmax = red[0];
    g_Q[bh * Nn + tid] = __expf(d - dmax);
    g_S[bh * Nn + tid] = __expf(0.2f * (d - dmax));
    float sv = g_src[bh * Nn + tid];
    float T = sv + dmax;
    float m = fmaxf(T, 0.2f * T);                      // exact row max of lrelu scores
    g_P[bh * Nn + tid] = __expf(T - m);
    g_Rr[bh * Nn + tid] = __expf(0.2f * T - m);
    g_thr[bh * Nn + tid] = -sv;
}

// ================== rowsum: den_i = sum_j w_ij, one warp per row ==================
__global__ __launch_bounds__(256) void rowsum_kernel() {
    int warp = threadIdx.x >> 5, lane = threadIdx.x & 31;
    int row = blockIdx.x * 8 + warp;                   // [0, BHt*Nn)
    int bh = row >> 10;
    float P = g_P[row], R = g_Rr[row], thr = g_thr[row];
    const float* D = g_dst + bh * Nn;
    const float* Q = g_Q + bh * Nn;
    const float* S = g_S + bh * Nn;
    float s = 0.f;
#pragma unroll 4
    for (int j = lane; j < Nn; j += 32) {
        float w = (__ldg(&D[j]) >= thr) ? P * __ldg(&Q[j]) : R * __ldg(&S[j]);
        s += w;
    }
#pragma unroll
    for (int o = 16; o > 0; o >>= 1) s += __shfl_down_sync(0xffffffffu, s, o);
    if (lane == 0) g_inv[row] = 1.0f / s;
}

// ================== attention GEMM: out = softmax-weights @ h ==================
// grid (8 i-tiles, 2 u-tiles, 32 bh), 256 threads (4 m-warps x 2 n-warps).
// A (weights) computed in registers in fragment layout; B = h^T staged from g_vt.
__global__ __launch_bounds__(256) void attn_mma_kernel(float* __restrict__ out) {
    __shared__ __nv_bfloat16 VTh[128][36];
    __shared__ __nv_bfloat16 VTl[128][36];
    __shared__ float Ds[Nn], Qs[Nn], Ss[Nn];
    __shared__ float Pn[128], Rn[128], Tn[128], In[128];

    int tid = threadIdx.x;
    int warp = tid >> 5, lane = tid & 31;
    int warp_m = warp & 3, warp_n = warp >> 2;
    int bh = blockIdx.z, b = bh >> 2, h = bh & 3;
    int i0 = blockIdx.x * 128, u0 = blockIdx.y * 128;

    for (int j = tid; j < Nn; j += 256) {
        Ds[j] = g_dst[bh * Nn + j];
        Qs[j] = g_Q[bh * Nn + j];
        Ss[j] = g_S[bh * Nn + j];
    }
    if (tid < 128) {
        Pn[tid] = g_P[bh * Nn + i0 + tid];
        Rn[tid] = g_Rr[bh * Nn + i0 + tid];
        Tn[tid] = g_thr[bh * Nn + i0 + tid];
        In[tid] = g_inv[bh * Nn + i0 + tid];
    }

    float acc[2][8][4];
#pragma unroll
    for (int mt = 0; mt < 2; mt++)
#pragma unroll
        for (int nt = 0; nt < 8; nt++)
#pragma unroll
            for (int q = 0; q < 4; q++) acc[mt][nt][q] = 0.f;

    // per-thread row constants (4 rows: warp_m*32 + mt*16 + (lane>>2) + {0,8})
    __syncthreads();
    float Pv[4], Rv[4], Tv[4];
#pragma unroll
    for (int q = 0; q < 4; q++) {
        int r = warp_m * 32 + (q >> 1) * 16 + (q & 1) * 8 + (lane >> 2);
        Pv[q] = Pn[r]; Rv[q] = Rn[r]; Tv[q] = Tn[r];
    }

    for (int st = 0; st < 32; st++) {                  // j stages of 32
        int j0 = st * 32;
        __syncthreads();
        {   // stage V^T slice [128 u][32 j] hi/lo
            int row = tid >> 1, half = tid & 1;
            size_t gb = ((size_t)bh * Uu + u0 + row) * Nn + j0 + half * 16;
            float4 vh0 = *(const float4*)(g_vt_hi + gb);
            float4 vh1 = *(const float4*)(g_vt_hi + gb + 8);
            float4 vl0 = *(const float4*)(g_vt_lo + gb);
            float4 vl1 = *(const float4*)(g_vt_lo + gb + 8);
            float2* dh = (float2*)&VTh[row][half * 16];
            float2* dl = (float2*)&VTl[row][half * 16];
            dh[0] = make_float2(vh0.x, vh0.y); dh[1] = make_float2(vh0.z, vh0.w);
            dh[2] = make_float2(vh1.x, vh1.y); dh[3] = make_float2(vh1.z, vh1.w);
            dl[0] = make_float2(vl0.x, vl0.y); dl[1] = make_float2(vl0.z, vl0.w);
            dl[2] = make_float2(vl1.x, vl1.y); dl[3] = make_float2(vl1.z, vl1.w);
        }
        __syncthreads();

#pragma unroll
        for (int kk = 0; kk < 2; kk++) {
            int c = j0 + kk * 16 + (lane & 3) * 2;     // global j of frag cols
            float2 Qa = *(float2*)&Qs[c], Qb = *(float2*)&Qs[c + 8];
            float2 Sa = *(float2*)&Ss[c], Sb = *(float2*)&Ss[c + 8];
            float2 Da = *(float2*)&Ds[c], Db = *(float2*)&Ds[c + 8];

            uint32_t aH[2][4], aL[2][4];
#pragma unroll
            for (int mt = 0; mt < 2; mt++) {
                int q0 = mt * 2, q1 = mt * 2 + 1;
                float w00 = (Da.x >= Tv[q0]) ? Pv[q0] * Qa.x : Rv[q0] * Sa.x;
                float w01 = (Da.y >= Tv[q0]) ? Pv[q0] * Qa.y : Rv[q0] * Sa.y;
                float w10 = (Da.x >= Tv[q1]) ? Pv[q1] * Qa.x : Rv[q1] * Sa.x;
                float w11 = (Da.y >= Tv[q1]) ? Pv[q1] * Qa.y : Rv[q1] * Sa.y;
                float w02 = (Db.x >= Tv[q0]) ? Pv[q0] * Qb.x : Rv[q0] * Sb.x;
                float w03 = (Db.y >= Tv[q0]) ? Pv[q0] * Qb.y : Rv[q0] * Sb.y;
                float w12 = (Db.x >= Tv[q1]) ? Pv[q1] * Qb.x : Rv[q1] * Sb.x;
                float w13 = (Db.y >= Tv[q1]) ? Pv[q1] * Qb.y : Rv[q1] * Sb.y;
                split_pack(w00, w01, aH[mt][0], aL[mt][0]);
                split_pack(w10, w11, aH[mt][1], aL[mt][1]);
                split_pack(w02, w03, aH[mt][2], aL[mt][2]);
                split_pack(w12, w13, aH[mt][3], aL[mt][3]);
            }
#pragma unroll
            for (int nt = 0; nt < 8; nt++) {
                int un = warp_n * 64 + nt * 8 + (lane >> 2);
                int kc = kk * 16 + (lane & 3) * 2;
                uint32_t bh0 = *(uint32_t*)&VTh[un][kc];
                uint32_t bh1 = *(uint32_t*)&VTh[un][kc + 8];
                uint32_t bl0 = *(uint32_t*)&VTl[un][kc];
                uint32_t bl1 = *(uint32_t*)&VTl[un][kc + 8];
#pragma unroll
                for (int mt = 0; mt < 2; mt++) {
                    mma16816(acc[mt][nt], aH[mt], bh0, bh1);
                    mma16816(acc[mt][nt], aL[mt], bh0, bh1);
                    mma16816(acc[mt][nt], aH[mt], bl0, bl1);
                }
            }
        }
    }

    // epilogue: normalize, write [B, N, H*U]
#pragma unroll
    for (int mt = 0; mt < 2; mt++) {
        int rl = warp_m * 32 + mt * 16 + (lane >> 2);
        int i_lo = i0 + rl;
        float inv0 = In[rl], inv1 = In[rl + 8];
#pragma unroll
        for (int nt = 0; nt < 8; nt++) {
            int u = u0 + warp_n * 64 + nt * 8 + (lane & 3) * 2;
            size_t o0 = ((size_t)(b * Nn + i_lo)) * (Hh * Uu) + h * Uu + u;
            size_t o1 = ((size_t)(b * Nn + i_lo + 8)) * (Hh * Uu) + h * Uu + u;
            *(float2*)&out[o0] = make_float2(acc[mt][nt][0] * inv0, acc[mt][nt][1] * inv0);
            *(float2*)&out[o1] = make_float2(acc[mt][nt][2] * inv1, acc[mt][nt][3] * inv1);
        }
    }
}

// ---------------------------------------------------------------------------
extern "C" void kernel_launch(void* const* d_in, const int* in_sizes, int n_in,
                              void* d_out, int out_size) {
    (void)in_sizes; (void)n_in; (void)out_size;
    const float* x     = (const float*)d_in[0];
    const float* W     = (const float*)d_in[1];
    const float* a_src = (const float*)d_in[2];
    const float* a_dst = (const float*)d_in[3];
    float* out = (float*)d_out;

    prep_wt_kernel<<<(Hh * Uu * Ff) / 256, 256>>>(W);
    proj_mma_kernel<<<dim3(8, 2, BHt), 256>>>(x);
    srcdst_kernel<<<(BHt * Nn) / 4, 128>>>(a_src, a_dst);
    transpose_split_kernel<<<dim3(Nn / 32, Uu / 32, BHt), dim3(32, 8)>>>();
    prep_pqrs_kernel<<<BHt, 1024>>>();
    rowsum_kernel<<<(BHt * Nn) / 8, 256>>>();
    attn_mma_kernel<<<dim3(8, 2, BHt), 256>>>(out);
}

// round 6
// speedup vs baseline: 2.0224x; 1.1389x over previous
#include <cuda_runtime.h>
#include <cuda_fp16.h>
#include <cstdint>

#define Bb 8
#define Nn 1024
#define Ff 256
#define Hh 4
#define Uu 256
#define BHt (Bb * Hh)

// ---------------- device scratch (static, no allocation) ----------------
__device__ float g_h[(size_t)BHt * Nn * Uu];        // fp32 projections [bh][n][u]
__device__ float g_src[BHt * Nn];
__device__ float g_dst[BHt * Nn];
__device__ __half g_vt_hi[(size_t)BHt * Uu * Nn];   // h^T split fp16 [bh][u][n]
__device__ __half g_vt_lo[(size_t)BHt * Uu * Nn];
__device__ __half g_wt_hi[Hh * Uu * Ff];            // W^T split fp16 [h][u][f]
__device__ __half g_wt_lo[Hh * Uu * Ff];
__device__ float g_Q[BHt * Nn];                     // exp(dst - dmax)
__device__ float g_S[BHt * Nn];                     // exp(0.2(dst - dmax))
__device__ float g_P[BHt * Nn];                     // exp(T - m), T = src + dmax
__device__ float g_Rr[BHt * Nn];                    // exp(0.2T - m)
__device__ float g_thr[BHt * Nn];                   // -src

// ---------------- helpers ----------------
__device__ __forceinline__ uint32_t pack_h2(float a, float b) {
    __half2 h = __floats2half2_rn(a, b);
    return *reinterpret_cast<uint32_t*>(&h);
}
__device__ __forceinline__ void split_pack_h(float w0, float w1, uint32_t& hi, uint32_t& lo) {
    __half h0 = __float2half_rn(w0), h1 = __float2half_rn(w1);
    float l0 = w0 - __half2float(h0);
    float l1 = w1 - __half2float(h1);
    __half2 hp = __halves2half2(h0, h1);
    hi = *reinterpret_cast<uint32_t*>(&hp);
    lo = pack_h2(l0, l1);
}
__device__ __forceinline__ void mma16816(float* c, const uint32_t* a, uint32_t b0, uint32_t b1) {
    asm volatile(
        "mma.sync.aligned.m16n8k16.row.col.f32.f16.f16.f32 "
        "{%0,%1,%2,%3}, {%4,%5,%6,%7}, {%8,%9}, {%0,%1,%2,%3};"
        : "+f"(c[0]), "+f"(c[1]), "+f"(c[2]), "+f"(c[3])
        : "r"(a[0]), "r"(a[1]), "r"(a[2]), "r"(a[3]), "r"(b0), "r"(b1));
}

// ================== prep: W^T split fp16 [h][u][f] ==================
__global__ __launch_bounds__(256) void prep_wt_kernel(const float* __restrict__ W) {
    int idx = blockIdx.x * 256 + threadIdx.x;
    int f = idx & 255, u = (idx >> 8) & 255, h = idx >> 16;
    float w = W[((size_t)(h * 256 + f)) * 256 + u];
    __half hi = __float2half_rn(w);
    __half lo = __float2half_rn(w - __half2float(hi));
    size_t o = ((size_t)(h * 256 + u)) * 256 + f;
    g_wt_hi[o] = hi;
    g_wt_lo[o] = lo;
}

// ================== proj: h = x @ W, mma.sync fp16 3-term ==================
// grid (8 i-tiles, 2 u-tiles, 32 bh), 256 threads (4 m-warps x 2 n-warps)
__global__ __launch_bounds__(256) void proj_mma_kernel(const float* __restrict__ x) {
    __shared__ float xs[32][132];
    __shared__ __half WTh[128][36];
    __shared__ __half WTl[128][36];

    int tid = threadIdx.x;
    int warp = tid >> 5, lane = tid & 31;
    int warp_m = warp & 3, warp_n = warp >> 2;
    int bh = blockIdx.z, b = bh >> 2, h = bh & 3;
    int i0 = blockIdx.x * 128, u0 = blockIdx.y * 128;

    float acc[2][8][4];
#pragma unroll
    for (int mt = 0; mt < 2; mt++)
#pragma unroll
        for (int nt = 0; nt < 8; nt++)
#pragma unroll
            for (int q = 0; q < 4; q++) acc[mt][nt][q] = 0.f;

    // prefetch registers
    float4 px[4];
    float4 pwh0, pwh1, pwl0, pwl1;
    int ld_row = tid >> 1, ld_half = tid & 1;

    // preload stage 0
#pragma unroll
    for (int it = 0; it < 4; it++) {
        int task = tid + it * 256;
        int i = task >> 3, c4 = (task & 7) << 2;
        px[it] = *(const float4*)&x[((size_t)(b * Nn + i0 + i)) * Ff + c4];
    }
    {
        size_t gb = ((size_t)(h * 256 + u0 + ld_row)) * 256 + ld_half * 16;
        pwh0 = *(const float4*)(g_wt_hi + gb);
        pwh1 = *(const float4*)(g_wt_hi + gb + 8);
        pwl0 = *(const float4*)(g_wt_lo + gb);
        pwl1 = *(const float4*)(g_wt_lo + gb + 8);
    }

    for (int st = 0; st < 8; st++) {
        __syncthreads();
        // store prefetched stage
#pragma unroll
        for (int it = 0; it < 4; it++) {
            int task = tid + it * 256;
            int i = task >> 3, c4 = (task & 7) << 2;
            xs[c4 + 0][i] = px[it].x;
            xs[c4 + 1][i] = px[it].y;
            xs[c4 + 2][i] = px[it].z;
            xs[c4 + 3][i] = px[it].w;
        }
        {
            float2* dh = (float2*)&WTh[ld_row][ld_half * 16];
            float2* dl = (float2*)&WTl[ld_row][ld_half * 16];
            dh[0] = make_float2(pwh0.x, pwh0.y); dh[1] = make_float2(pwh0.z, pwh0.w);
            dh[2] = make_float2(pwh1.x, pwh1.y); dh[3] = make_float2(pwh1.z, pwh1.w);
            dl[0] = make_float2(pwl0.x, pwl0.y); dl[1] = make_float2(pwl0.z, pwl0.w);
            dl[2] = make_float2(pwl1.x, pwl1.y); dl[3] = make_float2(pwl1.z, pwl1.w);
        }
        __syncthreads();

        // issue next-stage loads (overlap with MMA below)
        if (st + 1 < 8) {
            int f0n = (st + 1) * 32;
#pragma unroll
            for (int it = 0; it < 4; it++) {
                int task = tid + it * 256;
                int i = task >> 3, c4 = (task & 7) << 2;
                px[it] = *(const float4*)&x[((size_t)(b * Nn + i0 + i)) * Ff + f0n + c4];
            }
            size_t gb = ((size_t)(h * 256 + u0 + ld_row)) * 256 + f0n + ld_half * 16;
            pwh0 = *(const float4*)(g_wt_hi + gb);
            pwh1 = *(const float4*)(g_wt_hi + gb + 8);
            pwl0 = *(const float4*)(g_wt_lo + gb);
            pwl1 = *(const float4*)(g_wt_lo + gb + 8);
        }

#pragma unroll
        for (int kk = 0; kk < 2; kk++) {
            int c = kk * 16 + (lane & 3) * 2;
            uint32_t aH[2][4], aL[2][4];
#pragma unroll
            for (int mt = 0; mt < 2; mt++) {
                int r0 = warp_m * 32 + mt * 16 + (lane >> 2);
                int r1 = r0 + 8;
                split_pack_h(xs[c][r0],     xs[c + 1][r0], aH[mt][0], aL[mt][0]);
                split_pack_h(xs[c][r1],     xs[c + 1][r1], aH[mt][1], aL[mt][1]);
                split_pack_h(xs[c + 8][r0], xs[c + 9][r0], aH[mt][2], aL[mt][2]);
                split_pack_h(xs[c + 8][r1], xs[c + 9][r1], aH[mt][3], aL[mt][3]);
            }
#pragma unroll
            for (int nt = 0; nt < 8; nt++) {
                int un = warp_n * 64 + nt * 8 + (lane >> 2);
                int kc = kk * 16 + (lane & 3) * 2;
                uint32_t bh0 = *(uint32_t*)&WTh[un][kc];
                uint32_t bh1 = *(uint32_t*)&WTh[un][kc + 8];
                uint32_t bl0 = *(uint32_t*)&WTl[un][kc];
                uint32_t bl1 = *(uint32_t*)&WTl[un][kc + 8];
#pragma unroll
                for (int mt = 0; mt < 2; mt++) {
                    mma16816(acc[mt][nt], aH[mt], bh0, bh1);
                    mma16816(acc[mt][nt], aL[mt], bh0, bh1);
                    mma16816(acc[mt][nt], aH[mt], bl0, bl1);
                }
            }
        }
    }

#pragma unroll
    for (int mt = 0; mt < 2; mt++) {
        int i_lo = i0 + warp_m * 32 + mt * 16 + (lane >> 2);
#pragma unroll
        for (int nt = 0; nt < 8; nt++) {
            int u = u0 + warp_n * 64 + nt * 8 + (lane & 3) * 2;
            *(float2*)&g_h[((size_t)bh * Nn + i_lo) * Uu + u] =
                make_float2(acc[mt][nt][0], acc[mt][nt][1]);
            *(float2*)&g_h[((size_t)bh * Nn + i_lo + 8) * Uu + u] =
                make_float2(acc[mt][nt][2], acc[mt][nt][3]);
        }
    }
}

// ================== srcdst GEMV ==================
__global__ __launch_bounds__(128) void srcdst_kernel(const float* __restrict__ a_src,
                                                     const float* __restrict__ a_dst) {
    int warp = threadIdx.x >> 5, lane = threadIdx.x & 31;
    int row = blockIdx.x * 4 + warp;
    int h = (row / Nn) & 3;
    const float* hp = g_h + (size_t)row * Uu;
    const float* as = a_src + h * Uu;
    const float* ad = a_dst + h * Uu;
    float s1 = 0.f, s2 = 0.f;
#pragma unroll
    for (int u = lane * 4; u < Uu; u += 128) {
        float4 v = *(const float4*)&hp[u];
        float4 p = *(const float4*)&as[u];
        float4 q = *(const float4*)&ad[u];
        s1 += v.x * p.x + v.y * p.y + v.z * p.z + v.w * p.w;
        s2 += v.x * q.x + v.y * q.y + v.z * q.z + v.w * q.w;
    }
#pragma unroll
    for (int o = 16; o > 0; o >>= 1) {
        s1 += __shfl_down_sync(0xffffffffu, s1, o);
        s2 += __shfl_down_sync(0xffffffffu, s2, o);
    }
    if (lane == 0) { g_src[row] = s1; g_dst[row] = s2; }
}

// ================== transpose + split fp16: g_vt = split(h^T) ==================
__global__ __launch_bounds__(256) void transpose_split_kernel() {
    __shared__ float t[32][33];
    int bh = blockIdx.z;
    int n0 = blockIdx.x * 32, u0 = blockIdx.y * 32;
    int tx = threadIdx.x, ty = threadIdx.y;            // 32 x 8
#pragma unroll
    for (int r = 0; r < 32; r += 8)
        t[ty + r][tx] = g_h[((size_t)bh * Nn + n0 + ty + r) * Uu + u0 + tx];
    __syncthreads();
#pragma unroll
    for (int r = 0; r < 32; r += 8) {
        float v = t[tx][ty + r];
        __half hi = __float2half_rn(v);
        __half lo = __float2half_rn(v - __half2float(hi));
        size_t o = ((size_t)bh * Uu + u0 + ty + r) * Nn + n0 + tx;
        g_vt_hi[o] = hi;
        g_vt_lo[o] = lo;
    }
}

// ================== prep P/Q/R/S/thr per (b,h) ==================
__global__ __launch_bounds__(1024) void prep_pqrs_kernel() {
    __shared__ float red[1024];
    int bh = blockIdx.x, tid = threadIdx.x;
    float d = g_dst[bh * Nn + tid];
    red[tid] = d;
    __syncthreads();
    for (int s = 512; s > 0; s >>= 1) {
        if (tid < s) red[tid] = fmaxf(red[tid], red[tid + s]);
        __syncthreads();
    }
    float dmax = red[0];
    g_Q[bh * Nn + tid] = __expf(d - dmax);
    g_S[bh * Nn + tid] = __expf(0.2f * (d - dmax));
    float sv = g_src[bh * Nn + tid];
    float T = sv + dmax;
    float m = fmaxf(T, 0.2f * T);
    g_P[bh * Nn + tid] = __expf(T - m);
    g_Rr[bh * Nn + tid] = __expf(0.2f * T - m);
    g_thr[bh * Nn + tid] = -sv;
}

// ================== attention: out = norm(w) @ h, fp16 2-term, fused rowsum ==================
__global__ __launch_bounds__(256) void attn_mma_kernel(float* __restrict__ out) {
    __shared__ __half VTh[128][36];
    __shared__ __half VTl[128][36];
    __shared__ float Ds[Nn], Qs[Nn], Ss[Nn];
    __shared__ float Pn[128], Rn[128], Tn[128];

    int tid = threadIdx.x;
    int warp = tid >> 5, lane = tid & 31;
    int warp_m = warp & 3, warp_n = warp >> 2;
    int bh = blockIdx.z, b = bh >> 2, h = bh & 3;
    int i0 = blockIdx.x * 128, u0 = blockIdx.y * 128;

    for (int j = tid; j < Nn; j += 256) {
        Ds[j] = g_dst[bh * Nn + j];
        Qs[j] = g_Q[bh * Nn + j];
        Ss[j] = g_S[bh * Nn + j];
    }
    if (tid < 128) {
        Pn[tid] = g_P[bh * Nn + i0 + tid];
        Rn[tid] = g_Rr[bh * Nn + i0 + tid];
        Tn[tid] = g_thr[bh * Nn + i0 + tid];
    }

    float acc[2][8][4];
#pragma unroll
    for (int mt = 0; mt < 2; mt++)
#pragma unroll
        for (int nt = 0; nt < 8; nt++)
#pragma unroll
            for (int q = 0; q < 4; q++) acc[mt][nt][q] = 0.f;
    float rs[4] = {0.f, 0.f, 0.f, 0.f};               // per-owned-row sum of fp16-rounded w

    __syncthreads();
    float Pv[4], Rv[4], Tv[4];
#pragma unroll
    for (int q = 0; q < 4; q++) {
        int r = warp_m * 32 + (q >> 1) * 16 + (q & 1) * 8 + (lane >> 2);
        Pv[q] = Pn[r]; Rv[q] = Rn[r]; Tv[q] = Tn[r];
    }

    int ld_row = tid >> 1, ld_half = tid & 1;
    float4 pvh0, pvh1, pvl0, pvl1;
    {
        size_t gb = ((size_t)bh * Uu + u0 + ld_row) * Nn + ld_half * 16;
        pvh0 = *(const float4*)(g_vt_hi + gb);
        pvh1 = *(const float4*)(g_vt_hi + gb + 8);
        pvl0 = *(const float4*)(g_vt_lo + gb);
        pvl1 = *(const float4*)(g_vt_lo + gb + 8);
    }

    for (int st = 0; st < 32; st++) {
        int j0 = st * 32;
        __syncthreads();
        {
            float2* dh = (float2*)&VTh[ld_row][ld_half * 16];
            float2* dl = (float2*)&VTl[ld_row][ld_half * 16];
            dh[0] = make_float2(pvh0.x, pvh0.y); dh[1] = make_float2(pvh0.z, pvh0.w);
            dh[2] = make_float2(pvh1.x, pvh1.y); dh[3] = make_float2(pvh1.z, pvh1.w);
            dl[0] = make_float2(pvl0.x, pvl0.y); dl[1] = make_float2(pvl0.z, pvl0.w);
            dl[2] = make_float2(pvl1.x, pvl1.y); dl[3] = make_float2(pvl1.z, pvl1.w);
        }
        __syncthreads();

        if (st + 1 < 32) {
            size_t gb = ((size_t)bh * Uu + u0 + ld_row) * Nn + (j0 + 32) + ld_half * 16;
            pvh0 = *(const float4*)(g_vt_hi + gb);
            pvh1 = *(const float4*)(g_vt_hi + gb + 8);
            pvl0 = *(const float4*)(g_vt_lo + gb);
            pvl1 = *(const float4*)(g_vt_lo + gb + 8);
        }

#pragma unroll
        for (int kk = 0; kk < 2; kk++) {
            int c = j0 + kk * 16 + (lane & 3) * 2;
            float2 Qa = *(float2*)&Qs[c], Qb = *(float2*)&Qs[c + 8];
            float2 Sa = *(float2*)&Ss[c], Sb = *(float2*)&Ss[c + 8];
            float2 Da = *(float2*)&Ds[c], Db = *(float2*)&Ds[c + 8];

            uint32_t aW[2][4];
#pragma unroll
            for (int mt = 0; mt < 2; mt++) {
                int q0 = mt * 2, q1 = mt * 2 + 1;
                float w00 = (Da.x >= Tv[q0]) ? Pv[q0] * Qa.x : Rv[q0] * Sa.x;
                float w01 = (Da.y >= Tv[q0]) ? Pv[q0] * Qa.y : Rv[q0] * Sa.y;
                float w10 = (Da.x >= Tv[q1]) ? Pv[q1] * Qa.x : Rv[q1] * Sa.x;
                float w11 = (Da.y >= Tv[q1]) ? Pv[q1] * Qa.y : Rv[q1] * Sa.y;
                float w02 = (Db.x >= Tv[q0]) ? Pv[q0] * Qb.x : Rv[q0] * Sb.x;
                float w03 = (Db.y >= Tv[q0]) ? Pv[q0] * Qb.y : Rv[q0] * Sb.y;
                float w12 = (Db.x >= Tv[q1]) ? Pv[q1] * Qb.x : Rv[q1] * Sb.x;
                float w13 = (Db.y >= Tv[q1]) ? Pv[q1] * Qb.y : Rv[q1] * Sb.y;
                __half2 p0 = __floats2half2_rn(w00, w01);
                __half2 p1 = __floats2half2_rn(w10, w11);
                __half2 p2 = __floats2half2_rn(w02, w03);
                __half2 p3 = __floats2half2_rn(w12, w13);
                aW[mt][0] = *reinterpret_cast<uint32_t*>(&p0);
                aW[mt][1] = *reinterpret_cast<uint32_t*>(&p1);
                aW[mt][2] = *reinterpret_cast<uint32_t*>(&p2);
                aW[mt][3] = *reinterpret_cast<uint32_t*>(&p3);
                // denominator uses the SAME fp16-rounded weights (common-mode cancel)
                float2 f0 = __half22float2(p0), f2 = __half22float2(p2);
                float2 f1 = __half22float2(p1), f3 = __half22float2(p3);
                rs[q0] += (f0.x + f0.y) + (f2.x + f2.y);
                rs[q1] += (f1.x + f1.y) + (f3.x + f3.y);
            }
#pragma unroll
            for (int nt = 0; nt < 8; nt++) {
                int un = warp_n * 64 + nt * 8 + (lane >> 2);
                int kc = kk * 16 + (lane & 3) * 2;
                uint32_t bh0 = *(uint32_t*)&VTh[un][kc];
                uint32_t bh1 = *(uint32_t*)&VTh[un][kc + 8];
                uint32_t bl0 = *(uint32_t*)&VTl[un][kc];
                uint32_t bl1 = *(uint32_t*)&VTl[un][kc + 8];
#pragma unroll
                for (int mt = 0; mt < 2; mt++) {
                    mma16816(acc[mt][nt], aW[mt], bh0, bh1);
                    mma16816(acc[mt][nt], aW[mt], bl0, bl1);
                }
            }
        }
    }

    // reduce rowsums across the 4 quad lanes (lane&3) that share each row
#pragma unroll
    for (int q = 0; q < 4; q++) {
        rs[q] += __shfl_xor_sync(0xffffffffu, rs[q], 1);
        rs[q] += __shfl_xor_sync(0xffffffffu, rs[q], 2);
        rs[q] = 1.0f / rs[q];
    }

#pragma unroll
    for (int mt = 0; mt < 2; mt++) {
        int i_lo = i0 + warp_m * 32 + mt * 16 + (lane >> 2);
        float inv0 = rs[mt * 2], inv1 = rs[mt * 2 + 1];
#pragma unroll
        for (int nt = 0; nt < 8; nt++) {
            int u = u0 + warp_n * 64 + nt * 8 + (lane & 3) * 2;
            size_t o0 = ((size_t)(b * Nn + i_lo)) * (Hh * Uu) + h * Uu + u;
            size_t o1 = ((size_t)(b * Nn + i_lo + 8)) * (Hh * Uu) + h * Uu + u;
            *(float2*)&out[o0] = make_float2(acc[mt][nt][0] * inv0, acc[mt][nt][1] * inv0);
            *(float2*)&out[o1] = make_float2(acc[mt][nt][2] * inv1, acc[mt][nt][3] * inv1);
        }
    }
}

// ---------------------------------------------------------------------------
extern "C" void kernel_launch(void* const* d_in, const int* in_sizes, int n_in,
                              void* d_out, int out_size) {
    (void)in_sizes; (void)n_in; (void)out_size;
    const float* x     = (const float*)d_in[0];
    const float* W     = (const float*)d_in[1];
    const float* a_src = (const float*)d_in[2];
    const float* a_dst = (const float*)d_in[3];
    float* out = (float*)d_out;

    prep_wt_kernel<<<(Hh * Uu * Ff) / 256, 256>>>(W);
    proj_mma_kernel<<<dim3(8, 2, BHt), 256>>>(x);
    srcdst_kernel<<<(BHt * Nn) / 4, 128>>>(a_src, a_dst);
    transpose_split_kernel<<<dim3(Nn / 32, Uu / 32, BHt), dim3(32, 8)>>>();
    prep_pqrs_kernel<<<BHt, 1024>>>();
    attn_mma_kernel<<<dim3(8, 2, BHt), 256>>>(out);
}

// round 7
// speedup vs baseline: 2.6782x; 1.3243x over previous
#include <cuda_runtime.h>
#include <cuda_fp16.h>
#include <cstdint>

#define Bb 8
#define Nn 1024
#define Ff 256
#define Hh 4
#define Uu 256
#define BHt (Bb * Hh)

// ---------------- device scratch (static, no allocation) ----------------
__device__ float g_h[(size_t)BHt * Nn * Uu];        // fp32 projections [bh][n][u]
__device__ float g_src[BHt * Nn];
__device__ float g_dst[BHt * Nn];
__device__ __half g_vt[(size_t)BHt * Uu * Nn];      // h^T fp16 [bh][u][n] (single term)
__device__ __half g_wt_hi[Hh * Uu * Ff];            // W^T split fp16 [h][u][f]
__device__ __half g_wt_lo[Hh * Uu * Ff];
__device__ float g_Q[BHt * Nn];                     // exp(dst - dmax)
__device__ float g_S[BHt * Nn];                     // exp(0.2(dst - dmax))
__device__ float g_P[BHt * Nn];                     // exp(T - m), T = src + dmax
__device__ float g_Rr[BHt * Nn];                    // exp(0.2T - m)
__device__ float g_thr[BHt * Nn];                   // -src

// ---------------- helpers ----------------
__device__ __forceinline__ uint32_t pack_h2(float a, float b) {
    __half2 h = __floats2half2_rn(a, b);
    return *reinterpret_cast<uint32_t*>(&h);
}
__device__ __forceinline__ void split_pack_h(float w0, float w1, uint32_t& hi, uint32_t& lo) {
    __half h0 = __float2half_rn(w0), h1 = __float2half_rn(w1);
    float l0 = w0 - __half2float(h0);
    float l1 = w1 - __half2float(h1);
    __half2 hp = __halves2half2(h0, h1);
    hi = *reinterpret_cast<uint32_t*>(&hp);
    lo = pack_h2(l0, l1);
}
__device__ __forceinline__ void mma16816(float* c, const uint32_t* a, uint32_t b0, uint32_t b1) {
    asm volatile(
        "mma.sync.aligned.m16n8k16.row.col.f32.f16.f16.f32 "
        "{%0,%1,%2,%3}, {%4,%5,%6,%7}, {%8,%9}, {%0,%1,%2,%3};"
        : "+f"(c[0]), "+f"(c[1]), "+f"(c[2]), "+f"(c[3])
        : "r"(a[0]), "r"(a[1]), "r"(a[2]), "r"(a[3]), "r"(b0), "r"(b1));
}

// ================== prep: W^T split fp16 [h][u][f] ==================
__global__ __launch_bounds__(256) void prep_wt_kernel(const float* __restrict__ W) {
    int idx = blockIdx.x * 256 + threadIdx.x;
    int f = idx & 255, u = (idx >> 8) & 255, h = idx >> 16;
    float w = W[((size_t)(h * 256 + f)) * 256 + u];
    __half hi = __float2half_rn(w);
    __half lo = __float2half_rn(w - __half2float(hi));
    size_t o = ((size_t)(h * 256 + u)) * 256 + f;
    g_wt_hi[o] = hi;
    g_wt_lo[o] = lo;
}

// ================== proj: h = x @ W, mma.sync fp16 3-term ==================
__global__ __launch_bounds__(256) void proj_mma_kernel(const float* __restrict__ x) {
    __shared__ float xs[32][132];
    __shared__ __half WTh[128][36];
    __shared__ __half WTl[128][36];

    int tid = threadIdx.x;
    int warp = tid >> 5, lane = tid & 31;
    int warp_m = warp & 3, warp_n = warp >> 2;
    int bh = blockIdx.z, b = bh >> 2, h = bh & 3;
    int i0 = blockIdx.x * 128, u0 = blockIdx.y * 128;

    float acc[2][8][4];
#pragma unroll
    for (int mt = 0; mt < 2; mt++)
#pragma unroll
        for (int nt = 0; nt < 8; nt++)
#pragma unroll
            for (int q = 0; q < 4; q++) acc[mt][nt][q] = 0.f;

    float4 px[4];
    float4 pwh0, pwh1, pwl0, pwl1;
    int ld_row = tid >> 1, ld_half = tid & 1;

#pragma unroll
    for (int it = 0; it < 4; it++) {
        int task = tid + it * 256;
        int i = task >> 3, c4 = (task & 7) << 2;
        px[it] = *(const float4*)&x[((size_t)(b * Nn + i0 + i)) * Ff + c4];
    }
    {
        size_t gb = ((size_t)(h * 256 + u0 + ld_row)) * 256 + ld_half * 16;
        pwh0 = *(const float4*)(g_wt_hi + gb);
        pwh1 = *(const float4*)(g_wt_hi + gb + 8);
        pwl0 = *(const float4*)(g_wt_lo + gb);
        pwl1 = *(const float4*)(g_wt_lo + gb + 8);
    }

    for (int st = 0; st < 8; st++) {
        __syncthreads();
#pragma unroll
        for (int it = 0; it < 4; it++) {
            int task = tid + it * 256;
            int i = task >> 3, c4 = (task & 7) << 2;
            xs[c4 + 0][i] = px[it].x;
            xs[c4 + 1][i] = px[it].y;
            xs[c4 + 2][i] = px[it].z;
            xs[c4 + 3][i] = px[it].w;
        }
        {
            float2* dh = (float2*)&WTh[ld_row][ld_half * 16];
            float2* dl = (float2*)&WTl[ld_row][ld_half * 16];
            dh[0] = make_float2(pwh0.x, pwh0.y); dh[1] = make_float2(pwh0.z, pwh0.w);
            dh[2] = make_float2(pwh1.x, pwh1.y); dh[3] = make_float2(pwh1.z, pwh1.w);
            dl[0] = make_float2(pwl0.x, pwl0.y); dl[1] = make_float2(pwl0.z, pwl0.w);
            dl[2] = make_float2(pwl1.x, pwl1.y); dl[3] = make_float2(pwl1.z, pwl1.w);
        }
        __syncthreads();

        if (st + 1 < 8) {
            int f0n = (st + 1) * 32;
#pragma unroll
            for (int it = 0; it < 4; it++) {
                int task = tid + it * 256;
                int i = task >> 3, c4 = (task & 7) << 2;
                px[it] = *(const float4*)&x[((size_t)(b * Nn + i0 + i)) * Ff + f0n + c4];
            }
            size_t gb = ((size_t)(h * 256 + u0 + ld_row)) * 256 + f0n + ld_half * 16;
            pwh0 = *(const float4*)(g_wt_hi + gb);
            pwh1 = *(const float4*)(g_wt_hi + gb + 8);
            pwl0 = *(const float4*)(g_wt_lo + gb);
            pwl1 = *(const float4*)(g_wt_lo + gb + 8);
        }

#pragma unroll
        for (int kk = 0; kk < 2; kk++) {
            int c = kk * 16 + (lane & 3) * 2;
            uint32_t aH[2][4], aL[2][4];
#pragma unroll
            for (int mt = 0; mt < 2; mt++) {
                int r0 = warp_m * 32 + mt * 16 + (lane >> 2);
                int r1 = r0 + 8;
                split_pack_h(xs[c][r0],     xs[c + 1][r0], aH[mt][0], aL[mt][0]);
                split_pack_h(xs[c][r1],     xs[c + 1][r1], aH[mt][1], aL[mt][1]);
                split_pack_h(xs[c + 8][r0], xs[c + 9][r0], aH[mt][2], aL[mt][2]);
                split_pack_h(xs[c + 8][r1], xs[c + 9][r1], aH[mt][3], aL[mt][3]);
            }
#pragma unroll
            for (int nt = 0; nt < 8; nt++) {
                int un = warp_n * 64 + nt * 8 + (lane >> 2);
                int kc = kk * 16 + (lane & 3) * 2;
                uint32_t bh0 = *(uint32_t*)&WTh[un][kc];
                uint32_t bh1 = *(uint32_t*)&WTh[un][kc + 8];
                uint32_t bl0 = *(uint32_t*)&WTl[un][kc];
                uint32_t bl1 = *(uint32_t*)&WTl[un][kc + 8];
#pragma unroll
                for (int mt = 0; mt < 2; mt++) {
                    mma16816(acc[mt][nt], aH[mt], bh0, bh1);
                    mma16816(acc[mt][nt], aL[mt], bh0, bh1);
                    mma16816(acc[mt][nt], aH[mt], bl0, bl1);
                }
            }
        }
    }

#pragma unroll
    for (int mt = 0; mt < 2; mt++) {
        int i_lo = i0 + warp_m * 32 + mt * 16 + (lane >> 2);
#pragma unroll
        for (int nt = 0; nt < 8; nt++) {
            int u = u0 + warp_n * 64 + nt * 8 + (lane & 3) * 2;
            *(float2*)&g_h[((size_t)bh * Nn + i_lo) * Uu + u] =
                make_float2(acc[mt][nt][0], acc[mt][nt][1]);
            *(float2*)&g_h[((size_t)bh * Nn + i_lo + 8) * Uu + u] =
                make_float2(acc[mt][nt][2], acc[mt][nt][3]);
        }
    }
}

// ================== srcdst GEMV ==================
__global__ __launch_bounds__(128) void srcdst_kernel(const float* __restrict__ a_src,
                                                     const float* __restrict__ a_dst) {
    int warp = threadIdx.x >> 5, lane = threadIdx.x & 31;
    int row = blockIdx.x * 4 + warp;
    int h = (row / Nn) & 3;
    const float* hp = g_h + (size_t)row * Uu;
    const float* as = a_src + h * Uu;
    const float* ad = a_dst + h * Uu;
    float s1 = 0.f, s2 = 0.f;
#pragma unroll
    for (int u = lane * 4; u < Uu; u += 128) {
        float4 v = *(const float4*)&hp[u];
        float4 p = *(const float4*)&as[u];
        float4 q = *(const float4*)&ad[u];
        s1 += v.x * p.x + v.y * p.y + v.z * p.z + v.w * p.w;
        s2 += v.x * q.x + v.y * q.y + v.z * q.z + v.w * q.w;
    }
#pragma unroll
    for (int o = 16; o > 0; o >>= 1) {
        s1 += __shfl_down_sync(0xffffffffu, s1, o);
        s2 += __shfl_down_sync(0xffffffffu, s2, o);
    }
    if (lane == 0) { g_src[row] = s1; g_dst[row] = s2; }
}

// ================== transpose: g_vt = fp16(h^T) ==================
__global__ __launch_bounds__(256) void transpose_split_kernel() {
    __shared__ float t[32][33];
    int bh = blockIdx.z;
    int n0 = blockIdx.x * 32, u0 = blockIdx.y * 32;
    int tx = threadIdx.x, ty = threadIdx.y;            // 32 x 8
#pragma unroll
    for (int r = 0; r < 32; r += 8)
        t[ty + r][tx] = g_h[((size_t)bh * Nn + n0 + ty + r) * Uu + u0 + tx];
    __syncthreads();
#pragma unroll
    for (int r = 0; r < 32; r += 8) {
        float v = t[tx][ty + r];
        size_t o = ((size_t)bh * Uu + u0 + ty + r) * Nn + n0 + tx;
        g_vt[o] = __float2half_rn(v);
    }
}

// ================== prep P/Q/R/S/thr per (b,h) ==================
__global__ __launch_bounds__(1024) void prep_pqrs_kernel() {
    __shared__ float red[1024];
    int bh = blockIdx.x, tid = threadIdx.x;
    float d = g_dst[bh * Nn + tid];
    red[tid] = d;
    __syncthreads();
    for (int s = 512; s > 0; s >>= 1) {
        if (tid < s) red[tid] = fmaxf(red[tid], red[tid + s]);
        __syncthreads();
    }
    float dmax = red[0];
    g_Q[bh * Nn + tid] = __expf(d - dmax);
    g_S[bh * Nn + tid] = __expf(0.2f * (d - dmax));
    float sv = g_src[bh * Nn + tid];
    float T = sv + dmax;
    float m = fmaxf(T, 0.2f * T);
    g_P[bh * Nn + tid] = __expf(T - m);
    g_Rr[bh * Nn + tid] = __expf(0.2f * T - m);
    g_thr[bh * Nn + tid] = -sv;
}

// ================== attention: out = norm(w) @ h, fp16 single-V, fused rowsum ==================
__global__ __launch_bounds__(256) void attn_mma_kernel(float* __restrict__ out) {
    __shared__ __half VTh[128][36];
    __shared__ float Ds[Nn], Qs[Nn], Ss[Nn];
    __shared__ float Pn[128], Rn[128], Tn[128];

    int tid = threadIdx.x;
    int warp = tid >> 5, lane = tid & 31;
    int warp_m = warp & 3, warp_n = warp >> 2;
    int bh = blockIdx.z, b = bh >> 2, h = bh & 3;
    int i0 = blockIdx.x * 128, u0 = blockIdx.y * 128;

    for (int j = tid; j < Nn; j += 256) {
        Ds[j] = g_dst[bh * Nn + j];
        Qs[j] = g_Q[bh * Nn + j];
        Ss[j] = g_S[bh * Nn + j];
    }
    if (tid < 128) {
        Pn[tid] = g_P[bh * Nn + i0 + tid];
        Rn[tid] = g_Rr[bh * Nn + i0 + tid];
        Tn[tid] = g_thr[bh * Nn + i0 + tid];
    }

    float acc[2][8][4];
#pragma unroll
    for (int mt = 0; mt < 2; mt++)
#pragma unroll
        for (int nt = 0; nt < 8; nt++)
#pragma unroll
            for (int q = 0; q < 4; q++) acc[mt][nt][q] = 0.f;
    float rs[4] = {0.f, 0.f, 0.f, 0.f};

    __syncthreads();
    float Pv[4], Rv[4], Tv[4];
#pragma unroll
    for (int q = 0; q < 4; q++) {
        int r = warp_m * 32 + (q >> 1) * 16 + (q & 1) * 8 + (lane >> 2);
        Pv[q] = Pn[r]; Rv[q] = Rn[r]; Tv[q] = Tn[r];
    }

    int ld_row = tid >> 1, ld_half = tid & 1;
    float4 pvh0, pvh1;
    {
        size_t gb = ((size_t)bh * Uu + u0 + ld_row) * Nn + ld_half * 16;
        pvh0 = *(const float4*)(g_vt + gb);
        pvh1 = *(const float4*)(g_vt + gb + 8);
    }

    for (int st = 0; st < 32; st++) {
        int j0 = st * 32;
        __syncthreads();
        {
            float2* dh = (float2*)&VTh[ld_row][ld_half * 16];
            dh[0] = make_float2(pvh0.x, pvh0.y); dh[1] = make_float2(pvh0.z, pvh0.w);
            dh[2] = make_float2(pvh1.x, pvh1.y); dh[3] = make_float2(pvh1.z, pvh1.w);
        }
        __syncthreads();

        if (st + 1 < 32) {
            size_t gb = ((size_t)bh * Uu + u0 + ld_row) * Nn + (j0 + 32) + ld_half * 16;
            pvh0 = *(const float4*)(g_vt + gb);
            pvh1 = *(const float4*)(g_vt + gb + 8);
        }

#pragma unroll
        for (int kk = 0; kk < 2; kk++) {
            int c = j0 + kk * 16 + (lane & 3) * 2;
            float2 Qa = *(float2*)&Qs[c], Qb = *(float2*)&Qs[c + 8];
            float2 Sa = *(float2*)&Ss[c], Sb = *(float2*)&Ss[c + 8];
            float2 Da = *(float2*)&Ds[c], Db = *(float2*)&Ds[c + 8];

            uint32_t aW[2][4];
#pragma unroll
            for (int mt = 0; mt < 2; mt++) {
                int q0 = mt * 2, q1 = mt * 2 + 1;
                float w00 = (Da.x >= Tv[q0]) ? Pv[q0] * Qa.x : Rv[q0] * Sa.x;
                float w01 = (Da.y >= Tv[q0]) ? Pv[q0] * Qa.y : Rv[q0] * Sa.y;
                float w10 = (Da.x >= Tv[q1]) ? Pv[q1] * Qa.x : Rv[q1] * Sa.x;
                float w11 = (Da.y >= Tv[q1]) ? Pv[q1] * Qa.y : Rv[q1] * Sa.y;
                float w02 = (Db.x >= Tv[q0]) ? Pv[q0] * Qb.x : Rv[q0] * Sb.x;
                float w03 = (Db.y >= Tv[q0]) ? Pv[q0] * Qb.y : Rv[q0] * Sb.y;
                float w12 = (Db.x >= Tv[q1]) ? Pv[q1] * Qb.x : Rv[q1] * Sb.x;
                float w13 = (Db.y >= Tv[q1]) ? Pv[q1] * Qb.y : Rv[q1] * Sb.y;
                __half2 p0 = __floats2half2_rn(w00, w01);
                __half2 p1 = __floats2half2_rn(w10, w11);
                __half2 p2 = __floats2half2_rn(w02, w03);
                __half2 p3 = __floats2half2_rn(w12, w13);
                aW[mt][0] = *reinterpret_cast<uint32_t*>(&p0);
                aW[mt][1] = *reinterpret_cast<uint32_t*>(&p1);
                aW[mt][2] = *reinterpret_cast<uint32_t*>(&p2);
                aW[mt][3] = *reinterpret_cast<uint32_t*>(&p3);
                // denominator from the SAME fp16-rounded weights (common-mode cancel)
                float2 f0 = __half22float2(p0), f2 = __half22float2(p2);
                float2 f1 = __half22float2(p1), f3 = __half22float2(p3);
                rs[q0] += (f0.x + f0.y) + (f2.x + f2.y);
                rs[q1] += (f1.x + f1.y) + (f3.x + f3.y);
            }
#pragma unroll
            for (int nt = 0; nt < 8; nt++) {
                int un = warp_n * 64 + nt * 8 + (lane >> 2);
                int kc = kk * 16 + (lane & 3) * 2;
                uint32_t bh0 = *(uint32_t*)&VTh[un][kc];
                uint32_t bh1 = *(uint32_t*)&VTh[un][kc + 8];
#pragma unroll
                for (int mt = 0; mt < 2; mt++) {
                    mma16816(acc[mt][nt], aW[mt], bh0, bh1);
                }
            }
        }
    }

#pragma unroll
    for (int q = 0; q < 4; q++) {
        rs[q] += __shfl_xor_sync(0xffffffffu, rs[q], 1);
        rs[q] += __shfl_xor_sync(0xffffffffu, rs[q], 2);
        rs[q] = 1.0f / rs[q];
    }

#pragma unroll
    for (int mt = 0; mt < 2; mt++) {
        int i_lo = i0 + warp_m * 32 + mt * 16 + (lane >> 2);
        float inv0 = rs[mt * 2], inv1 = rs[mt * 2 + 1];
#pragma unroll
        for (int nt = 0; nt < 8; nt++) {
            int u = u0 + warp_n * 64 + nt * 8 + (lane & 3) * 2;
            size_t o0 = ((size_t)(b * Nn + i_lo)) * (Hh * Uu) + h * Uu + u;
            size_t o1 = ((size_t)(b * Nn + i_lo + 8)) * (Hh * Uu) + h * Uu + u;
            *(float2*)&out[o0] = make_float2(acc[mt][nt][0] * inv0, acc[mt][nt][1] * inv0);
            *(float2*)&out[o1] = make_float2(acc[mt][nt][2] * inv1, acc[mt][nt][3] * inv1);
        }
    }
}

// ---------------------------------------------------------------------------
extern "C" void kernel_launch(void* const* d_in, const int* in_sizes, int n_in,
                              void* d_out, int out_size) {
    (void)in_sizes; (void)n_in; (void)out_size;
    const float* x     = (const float*)d_in[0];
    const float* W     = (const float*)d_in[1];
    const float* a_src = (const float*)d_in[2];
    const float* a_dst = (const float*)d_in[3];
    float* out = (float*)d_out;

    prep_wt_kernel<<<(Hh * Uu * Ff) / 256, 256>>>(W);
    proj_mma_kernel<<<dim3(8, 2, BHt), 256>>>(x);
    srcdst_kernel<<<(BHt * Nn) / 4, 128>>>(a_src, a_dst);
    transpose_split_kernel<<<dim3(Nn / 32, Uu / 32, BHt), dim3(32, 8)>>>();
    prep_pqrs_kernel<<<BHt, 1024>>>();
    attn_mma_kernel<<<dim3(8, 2, BHt), 256>>>(out);
}

// round 8
// speedup vs baseline: 3.2980x; 1.2314x over previous
#include <cuda_runtime.h>
#include <cuda_fp16.h>
#include <cstdint>

#define Bb 8
#define Nn 1024
#define Ff 256
#define Hh 4
#define Uu 256
#define BHt (Bb * Hh)

// ---------------- device scratch (static, no allocation) ----------------
__device__ __half g_vt[(size_t)BHt * Uu * Nn];      // h^T fp16 [bh][u][n]
__device__ __half g_wt_hi[Hh * Uu * Ff];            // W^T split fp16 [h][u][f]
__device__ __half g_wt_lo[Hh * Uu * Ff];
__device__ float g_srcp[2 * BHt * Nn];              // partial src dots [uhalf][bh*N+n]
__device__ float g_dstp[2 * BHt * Nn];
__device__ __half g_Qh[BHt * Nn];                   // fp16 exp(dst - dmax)
__device__ __half g_Sh[BHt * Nn];                   // fp16 exp(0.2(dst - dmax))
__device__ __half g_Dh[BHt * Nn];                   // fp16 dst
__device__ __half g_Ph[BHt * Nn];                   // fp16 exp(T - m)
__device__ __half g_Rh[BHt * Nn];                   // fp16 exp(0.2T - m)
__device__ __half g_Th[BHt * Nn];                   // fp16 -src (threshold)

// ---------------- helpers ----------------
__device__ __forceinline__ uint32_t pack_h2(float a, float b) {
    __half2 h = __floats2half2_rn(a, b);
    return *reinterpret_cast<uint32_t*>(&h);
}
__device__ __forceinline__ void split_pack_h(float w0, float w1, uint32_t& hi, uint32_t& lo) {
    __half h0 = __float2half_rn(w0), h1 = __float2half_rn(w1);
    float l0 = w0 - __half2float(h0);
    float l1 = w1 - __half2float(h1);
    __half2 hp = __halves2half2(h0, h1);
    hi = *reinterpret_cast<uint32_t*>(&hp);
    lo = pack_h2(l0, l1);
}
__device__ __forceinline__ void mma16816(float* c, const uint32_t* a, uint32_t b0, uint32_t b1) {
    asm volatile(
        "mma.sync.aligned.m16n8k16.row.col.f32.f16.f16.f32 "
        "{%0,%1,%2,%3}, {%4,%5,%6,%7}, {%8,%9}, {%0,%1,%2,%3};"
        : "+f"(c[0]), "+f"(c[1]), "+f"(c[2]), "+f"(c[3])
        : "r"(a[0]), "r"(a[1]), "r"(a[2]), "r"(a[3]), "r"(b0), "r"(b1));
}

// ================== prep: W^T split fp16 [h][u][f] ==================
__global__ __launch_bounds__(256) void prep_wt_kernel(const float* __restrict__ W) {
    int idx = blockIdx.x * 256 + threadIdx.x;
    int f = idx & 255, u = (idx >> 8) & 255, h = idx >> 16;
    float w = W[((size_t)(h * 256 + f)) * 256 + u];
    __half hi = __float2half_rn(w);
    __half lo = __float2half_rn(w - __half2float(hi));
    size_t o = ((size_t)(h * 256 + u)) * 256 + f;
    g_wt_hi[o] = hi;
    g_wt_lo[o] = lo;
}

// ================== proj: h = x @ W (fp16 3-term) + fused src/dst partials
// ================== + fused fp16 transpose into g_vt. No g_h.
__global__ __launch_bounds__(256) void proj_mma_kernel(const float* __restrict__ x,
                                                       const float* __restrict__ a_src,
                                                       const float* __restrict__ a_dst) {
    static __shared__ __align__(16) char pbuf[35328];
    float (*xs)[132]   = (float (*)[132])pbuf;                 // 16896 B
    __half (*WTh)[36]  = (__half (*)[36])(pbuf + 16896);       //  9216 B
    __half (*WTl)[36]  = (__half (*)[36])(pbuf + 26112);       //  9216 B
    __half (*tr)[136]  = (__half (*)[136])pbuf;                // epilogue overlay (34816 B)
    __shared__ float sred[2][2][128];                          // [src/dst][warp_n][row]

    int tid = threadIdx.x;
    int warp = tid >> 5, lane = tid & 31;
    int warp_m = warp & 3, warp_n = warp >> 2;
    int bh = blockIdx.z, b = bh >> 2, h = bh & 3;
    int i0 = blockIdx.x * 128, u0 = blockIdx.y * 128;

    float acc[2][8][4];
#pragma unroll
    for (int mt = 0; mt < 2; mt++)
#pragma unroll
        for (int nt = 0; nt < 8; nt++)
#pragma unroll
            for (int q = 0; q < 4; q++) acc[mt][nt][q] = 0.f;

    float4 px[4];
    float4 pwh0, pwh1, pwl0, pwl1;
    int ld_row = tid >> 1, ld_half = tid & 1;

#pragma unroll
    for (int it = 0; it < 4; it++) {
        int task = tid + it * 256;
        int i = task >> 3, c4 = (task & 7) << 2;
        px[it] = *(const float4*)&x[((size_t)(b * Nn + i0 + i)) * Ff + c4];
    }
    {
        size_t gb = ((size_t)(h * 256 + u0 + ld_row)) * 256 + ld_half * 16;
        pwh0 = *(const float4*)(g_wt_hi + gb);
        pwh1 = *(const float4*)(g_wt_hi + gb + 8);
        pwl0 = *(const float4*)(g_wt_lo + gb);
        pwl1 = *(const float4*)(g_wt_lo + gb + 8);
    }

    for (int st = 0; st < 8; st++) {
        __syncthreads();
#pragma unroll
        for (int it = 0; it < 4; it++) {
            int task = tid + it * 256;
            int i = task >> 3, c4 = (task & 7) << 2;
            xs[c4 + 0][i] = px[it].x;
            xs[c4 + 1][i] = px[it].y;
            xs[c4 + 2][i] = px[it].z;
            xs[c4 + 3][i] = px[it].w;
        }
        {
            float2* dh = (float2*)&WTh[ld_row][ld_half * 16];
            float2* dl = (float2*)&WTl[ld_row][ld_half * 16];
            dh[0] = make_float2(pwh0.x, pwh0.y); dh[1] = make_float2(pwh0.z, pwh0.w);
            dh[2] = make_float2(pwh1.x, pwh1.y); dh[3] = make_float2(pwh1.z, pwh1.w);
            dl[0] = make_float2(pwl0.x, pwl0.y); dl[1] = make_float2(pwl0.z, pwl0.w);
            dl[2] = make_float2(pwl1.x, pwl1.y); dl[3] = make_float2(pwl1.z, pwl1.w);
        }
        __syncthreads();

        if (st + 1 < 8) {
            int f0n = (st + 1) * 32;
#pragma unroll
            for (int it = 0; it < 4; it++) {
                int task = tid + it * 256;
                int i = task >> 3, c4 = (task & 7) << 2;
                px[it] = *(const float4*)&x[((size_t)(b * Nn + i0 + i)) * Ff + f0n + c4];
            }
            size_t gb = ((size_t)(h * 256 + u0 + ld_row)) * 256 + f0n + ld_half * 16;
            pwh0 = *(const float4*)(g_wt_hi + gb);
            pwh1 = *(const float4*)(g_wt_hi + gb + 8);
            pwl0 = *(const float4*)(g_wt_lo + gb);
            pwl1 = *(const float4*)(g_wt_lo + gb + 8);
        }

#pragma unroll
        for (int kk = 0; kk < 2; kk++) {
            int c = kk * 16 + (lane & 3) * 2;
            uint32_t aH[2][4], aL[2][4];
#pragma unroll
            for (int mt = 0; mt < 2; mt++) {
                int r0 = warp_m * 32 + mt * 16 + (lane >> 2);
                int r1 = r0 + 8;
                split_pack_h(xs[c][r0],     xs[c + 1][r0], aH[mt][0], aL[mt][0]);
                split_pack_h(xs[c][r1],     xs[c + 1][r1], aH[mt][1], aL[mt][1]);
                split_pack_h(xs[c + 8][r0], xs[c + 9][r0], aH[mt][2], aL[mt][2]);
                split_pack_h(xs[c + 8][r1], xs[c + 9][r1], aH[mt][3], aL[mt][3]);
            }
#pragma unroll
            for (int nt = 0; nt < 8; nt++) {
                int un = warp_n * 64 + nt * 8 + (lane >> 2);
                int kc = kk * 16 + (lane & 3) * 2;
                uint32_t bh0 = *(uint32_t*)&WTh[un][kc];
                uint32_t bh1 = *(uint32_t*)&WTh[un][kc + 8];
                uint32_t bl0 = *(uint32_t*)&WTl[un][kc];
                uint32_t bl1 = *(uint32_t*)&WTl[un][kc + 8];
#pragma unroll
                for (int mt = 0; mt < 2; mt++) {
                    mma16816(acc[mt][nt], aH[mt], bh0, bh1);
                    mma16816(acc[mt][nt], aL[mt], bh0, bh1);
                    mma16816(acc[mt][nt], aH[mt], bl0, bl1);
                }
            }
        }
    }

    // ---- epilogue A: partial src/dst dot over this CTA's 128 u-columns ----
    {
        float s1[4] = {0.f, 0.f, 0.f, 0.f};
        float s2[4] = {0.f, 0.f, 0.f, 0.f};
#pragma unroll
        for (int nt = 0; nt < 8; nt++) {
            int u = u0 + warp_n * 64 + nt * 8 + (lane & 3) * 2;
            float2 as = *(const float2*)&a_src[h * 256 + u];
            float2 ad = *(const float2*)&a_dst[h * 256 + u];
#pragma unroll
            for (int mt = 0; mt < 2; mt++) {
                s1[mt * 2 + 0] += acc[mt][nt][0] * as.x + acc[mt][nt][1] * as.y;
                s1[mt * 2 + 1] += acc[mt][nt][2] * as.x + acc[mt][nt][3] * as.y;
                s2[mt * 2 + 0] += acc[mt][nt][0] * ad.x + acc[mt][nt][1] * ad.y;
                s2[mt * 2 + 1] += acc[mt][nt][2] * ad.x + acc[mt][nt][3] * ad.y;
            }
        }
#pragma unroll
        for (int q = 0; q < 4; q++) {
            s1[q] += __shfl_xor_sync(0xffffffffu, s1[q], 1);
            s1[q] += __shfl_xor_sync(0xffffffffu, s1[q], 2);
            s2[q] += __shfl_xor_sync(0xffffffffu, s2[q], 1);
            s2[q] += __shfl_xor_sync(0xffffffffu, s2[q], 2);
        }
        if ((lane & 3) == 0) {
#pragma unroll
            for (int q = 0; q < 4; q++) {
                int r = warp_m * 32 + (q >> 1) * 16 + (q & 1) * 8 + (lane >> 2);
                sred[0][warp_n][r] = s1[q];
                sred[1][warp_n][r] = s2[q];
            }
        }
    }
    __syncthreads();
    if (tid < 128) {
        size_t o = (size_t)blockIdx.y * (BHt * Nn) + bh * Nn + i0 + tid;
        g_srcp[o] = sred[0][0][tid] + sred[0][1][tid];
        g_dstp[o] = sred[1][0][tid] + sred[1][1][tid];
    }
    __syncthreads();   // done reading xs/WT; safe to overlay tr

    // ---- epilogue B: fp16 transpose restage -> g_vt [u][n] ----
#pragma unroll
    for (int mt = 0; mt < 2; mt++) {
        int i_loc = warp_m * 32 + mt * 16 + (lane >> 2);
#pragma unroll
        for (int nt = 0; nt < 8; nt++) {
            int u_loc = warp_n * 64 + nt * 8 + (lane & 3) * 2;
            tr[u_loc][i_loc]         = __float2half_rn(acc[mt][nt][0]);
            tr[u_loc + 1][i_loc]     = __float2half_rn(acc[mt][nt][1]);
            tr[u_loc][i_loc + 8]     = __float2half_rn(acc[mt][nt][2]);
            tr[u_loc + 1][i_loc + 8] = __float2half_rn(acc[mt][nt][3]);
        }
    }
    __syncthreads();
    {
        int row = tid >> 1, seg = tid & 1;
        const float4* srcp = (const float4*)&tr[row][seg * 64];
        float4* dstp = (float4*)&g_vt[((size_t)bh * Uu + u0 + row) * Nn + i0 + seg * 64];
#pragma unroll
        for (int k = 0; k < 8; k++) dstp[k] = srcp[k];
    }
}

// ================== prep: combine partials, P/Q/R/S/thr fp16 per (b,h) ==================
__global__ __launch_bounds__(1024) void prep_pqrs_kernel() {
    __shared__ float red[1024];
    int bh = blockIdx.x, tid = threadIdx.x;
    int row = bh * Nn + tid;
    float d = g_dstp[row] + g_dstp[BHt * Nn + row];
    float sv = g_srcp[row] + g_srcp[BHt * Nn + row];
    red[tid] = d;
    __syncthreads();
    for (int s = 512; s > 0; s >>= 1) {
        if (tid < s) red[tid] = fmaxf(red[tid], red[tid + s]);
        __syncthreads();
    }
    float dmax = red[0];
    g_Qh[row] = __float2half_rn(__expf(d - dmax));
    g_Sh[row] = __float2half_rn(__expf(0.2f * (d - dmax)));
    g_Dh[row] = __float2half_rn(d);
    float T = sv + dmax;
    float m = fmaxf(T, 0.2f * T);
    g_Ph[row] = __float2half_rn(__expf(T - m));
    g_Rh[row] = __float2half_rn(__expf(0.2f * T - m));
    g_Th[row] = __float2half_rn(-sv);
}

// ================== attention: half2 weight-gen, fp16 single-V, fused rowsum ==================
__global__ __launch_bounds__(256) void attn_mma_kernel(float* __restrict__ out) {
    __shared__ __half VTh[128][36];
    __shared__ __half Dsh[Nn], Qsh[Nn], Ssh[Nn];
    __shared__ __half Pn[128], Rn[128], Tn[128];

    int tid = threadIdx.x;
    int warp = tid >> 5, lane = tid & 31;
    int warp_m = warp & 3, warp_n = warp >> 2;
    int bh = blockIdx.z, b = bh >> 2, h = bh & 3;
    int i0 = blockIdx.x * 128, u0 = blockIdx.y * 128;

    for (int j = tid; j < Nn; j += 256) {
        Dsh[j] = g_Dh[bh * Nn + j];
        Qsh[j] = g_Qh[bh * Nn + j];
        Ssh[j] = g_Sh[bh * Nn + j];
    }
    if (tid < 128) {
        Pn[tid] = g_Ph[bh * Nn + i0 + tid];
        Rn[tid] = g_Rh[bh * Nn + i0 + tid];
        Tn[tid] = g_Th[bh * Nn + i0 + tid];
    }

    float acc[2][8][4];
#pragma unroll
    for (int mt = 0; mt < 2; mt++)
#pragma unroll
        for (int nt = 0; nt < 8; nt++)
#pragma unroll
            for (int q = 0; q < 4; q++) acc[mt][nt][q] = 0.f;
    float rs[4] = {0.f, 0.f, 0.f, 0.f};

    __syncthreads();
    __half2 Pv[4], Rv[4], Tv[4];
#pragma unroll
    for (int q = 0; q < 4; q++) {
        int r = warp_m * 32 + (q >> 1) * 16 + (q & 1) * 8 + (lane >> 2);
        Pv[q] = __half2half2(Pn[r]);
        Rv[q] = __half2half2(Rn[r]);
        Tv[q] = __half2half2(Tn[r]);
    }

    int ld_row = tid >> 1, ld_half = tid & 1;
    float4 pvh0, pvh1;
    {
        size_t gb = ((size_t)bh * Uu + u0 + ld_row) * Nn + ld_half * 16;
        pvh0 = *(const float4*)(g_vt + gb);
        pvh1 = *(const float4*)(g_vt + gb + 8);
    }

    for (int st = 0; st < 32; st++) {
        int j0 = st * 32;
        __syncthreads();
        {
            float2* dh = (float2*)&VTh[ld_row][ld_half * 16];
            dh[0] = make_float2(pvh0.x, pvh0.y); dh[1] = make_float2(pvh0.z, pvh0.w);
            dh[2] = make_float2(pvh1.x, pvh1.y); dh[3] = make_float2(pvh1.z, pvh1.w);
        }
        __syncthreads();

        if (st + 1 < 32) {
            size_t gb = ((size_t)bh * Uu + u0 + ld_row) * Nn + (j0 + 32) + ld_half * 16;
            pvh0 = *(const float4*)(g_vt + gb);
            pvh1 = *(const float4*)(g_vt + gb + 8);
        }

#pragma unroll
        for (int kk = 0; kk < 2; kk++) {
            int c = j0 + kk * 16 + (lane & 3) * 2;
            __half2 Qa = *(const __half2*)&Qsh[c], Qb = *(const __half2*)&Qsh[c + 8];
            __half2 Sa = *(const __half2*)&Ssh[c], Sb = *(const __half2*)&Ssh[c + 8];
            __half2 Da = *(const __half2*)&Dsh[c], Db = *(const __half2*)&Dsh[c + 8];

            uint32_t aW[2][4];
#pragma unroll
            for (int mt = 0; mt < 2; mt++) {
#pragma unroll
                for (int dq = 0; dq < 2; dq++) {
                    int q = mt * 2 + dq;
                    // w = mask ? P*Q : R*S   (mask = dst >= thr, fp16 — continuity at
                    // the lrelu kink makes boundary misclassification harmless)
                    __half2 mA = __hge2(Da, Tv[q]);
                    __half2 wPa = __hmul2(Pv[q], Qa);
                    __half2 wRa = __hmul2(Rv[q], Sa);
                    __half2 wa = __hfma2(__hsub2(wPa, wRa), mA, wRa);
                    __half2 mB = __hge2(Db, Tv[q]);
                    __half2 wPb = __hmul2(Pv[q], Qb);
                    __half2 wRb = __hmul2(Rv[q], Sb);
                    __half2 wb = __hfma2(__hsub2(wPb, wRb), mB, wRb);
                    aW[mt][dq]     = *reinterpret_cast<uint32_t*>(&wa);
                    aW[mt][dq + 2] = *reinterpret_cast<uint32_t*>(&wb);
                    __half2 hsum = __hadd2(wa, wb);
                    float2 f = __half22float2(hsum);
                    rs[q] += f.x + f.y;
                }
            }
#pragma unroll
            for (int nt = 0; nt < 8; nt++) {
                int un = warp_n * 64 + nt * 8 + (lane >> 2);
                int kc = kk * 16 + (lane & 3) * 2;
                uint32_t bh0 = *(uint32_t*)&VTh[un][kc];
                uint32_t bh1 = *(uint32_t*)&VTh[un][kc + 8];
#pragma unroll
                for (int mt = 0; mt < 2; mt++) {
                    mma16816(acc[mt][nt], aW[mt], bh0, bh1);
                }
            }
        }
    }

#pragma unroll
    for (int q = 0; q < 4; q++) {
        rs[q] += __shfl_xor_sync(0xffffffffu, rs[q], 1);
        rs[q] += __shfl_xor_sync(0xffffffffu, rs[q], 2);
        rs[q] = 1.0f / rs[q];
    }

#pragma unroll
    for (int mt = 0; mt < 2; mt++) {
        int i_lo = i0 + warp_m * 32 + mt * 16 + (lane >> 2);
        float inv0 = rs[mt * 2], inv1 = rs[mt * 2 + 1];
#pragma unroll
        for (int nt = 0; nt < 8; nt++) {
            int u = u0 + warp_n * 64 + nt * 8 + (lane & 3) * 2;
            size_t o0 = ((size_t)(b * Nn + i_lo)) * (Hh * Uu) + h * Uu + u;
            size_t o1 = ((size_t)(b * Nn + i_lo + 8)) * (Hh * Uu) + h * Uu + u;
            *(float2*)&out[o0] = make_float2(acc[mt][nt][0] * inv0, acc[mt][nt][1] * inv0);
            *(float2*)&out[o1] = make_float2(acc[mt][nt][2] * inv1, acc[mt][nt][3] * inv1);
        }
    }
}

// ---------------------------------------------------------------------------
extern "C" void kernel_launch(void* const* d_in, const int* in_sizes, int n_in,
                              void* d_out, int out_size) {
    (void)in_sizes; (void)n_in; (void)out_size;
    const float* x     = (const float*)d_in[0];
    const float* W     = (const float*)d_in[1];
    const float* a_src = (const float*)d_in[2];
    const float* a_dst = (const float*)d_in[3];
    float* out = (float*)d_out;

    prep_wt_kernel<<<(Hh * Uu * Ff) / 256, 256>>>(W);
    proj_mma_kernel<<<dim3(8, 2, BHt), 256>>>(x, a_src, a_dst);
    prep_pqrs_kernel<<<BHt, 1024>>>();
    attn_mma_kernel<<<dim3(8, 2, BHt), 256>>>(out);
}